// round 2
// baseline (speedup 1.0000x reference)
#include <cuda_runtime.h>
#include <math.h>

// Problem constants
#define BB 4
#define CC 256
#define HH 64
#define WW 64
#define HW 4096          // 64*64
#define CR 16            // C/16 hidden
#define C8 32            // C/8

// ---------------- scratch (static device globals; no runtime alloc) ----------
__device__ float g_avg[BB * CC];
__device__ float g_max[BB * CC];
__device__ float g_chatt[BB * CC];
__device__ float g_avgs[BB * HW];
__device__ float g_maxs[BB * HW];
// fallback scratch (only touched if gamma != 0, which setup_inputs never produces)
__device__ float g_q[BB * C8 * HW];
__device__ float g_k[BB * C8 * HW];
__device__ float g_v[BB * CC * HW];

// ---------------- Kernel A: per-(b,c) global avg + max pool ------------------
// grid = 1024 blocks (one per (b,c)), 256 threads; each thread 4 float4 loads.
__global__ void sca_pool_bc(const float* __restrict__ x) {
    int bc = blockIdx.x;                       // 0..1023
    const float4* p = (const float4*)(x + (size_t)bc * HW);
    float s = 0.f, m = -INFINITY;
#pragma unroll
    for (int i = 0; i < 4; ++i) {
        float4 v = p[threadIdx.x + i * 256];
        s += (v.x + v.y) + (v.z + v.w);
        m = fmaxf(m, fmaxf(fmaxf(v.x, v.y), fmaxf(v.z, v.w)));
    }
    __shared__ float ss[256], sm[256];
    ss[threadIdx.x] = s; sm[threadIdx.x] = m;
    __syncthreads();
    for (int off = 128; off > 0; off >>= 1) {
        if (threadIdx.x < off) {
            ss[threadIdx.x] += ss[threadIdx.x + off];
            sm[threadIdx.x] = fmaxf(sm[threadIdx.x], sm[threadIdx.x + off]);
        }
        __syncthreads();
    }
    if (threadIdx.x == 0) {
        g_avg[bc] = ss[0] * (1.f / (float)HW);
        g_max[bc] = sm[0];
    }
}

// ---------------- Kernel B: channel MLP + sigmoid ----------------------------
// grid = 4 blocks (one per batch), 256 threads.
__global__ void sca_mlp(const float* __restrict__ w1, const float* __restrict__ w2) {
    int bb = blockIdx.x;
    int t = threadIdx.x;
    __shared__ float a[CC], mm[CC], h[2 * CR];
    a[t]  = g_avg[bb * CC + t];
    mm[t] = g_max[bb * CC + t];
    __syncthreads();
    if (t < 2 * CR) {
        const float* v = (t < CR) ? a : mm;
        int j = t & (CR - 1);
        float s = 0.f;
#pragma unroll 8
        for (int c = 0; c < CC; ++c) s += v[c] * w1[j * CC + c];
        h[t] = fmaxf(s, 0.f);
    }
    __syncthreads();
    float s = 0.f;
#pragma unroll
    for (int j = 0; j < CR; ++j) s += w2[t * CR + j] * (h[j] + h[CR + j]);
    g_chatt[bb * CC + t] = 1.f / (1.f + __expf(-s));
}

// ---------------- Kernel C: per-pixel channel mean/max of x*ch_att -----------
// grid = 4*32 = 128 blocks, blockDim (128,4). Thread (tx,ty) handles pixel
// tile*128+tx, channels [ty*64, ty*64+64).
__global__ void sca_spstats(const float* __restrict__ x) {
    int bb   = blockIdx.x >> 5;
    int tile = blockIdx.x & 31;
    int tx = threadIdx.x, ty = threadIdx.y;
    int pix = tile * 128 + tx;
    __shared__ float ch[CC];
    int tid = ty * 128 + tx;
    if (tid < CC) ch[tid] = g_chatt[bb * CC + tid];
    __syncthreads();
    const float* xb = x + (size_t)bb * CC * HW + pix;
    float s = 0.f, m = -INFINITY;
    int c0 = ty * 64;
#pragma unroll 8
    for (int c = c0; c < c0 + 64; ++c) {
        float v = xb[c * HW] * ch[c];
        s += v; m = fmaxf(m, v);
    }
    __shared__ float ps[4][128], pm[4][128];
    ps[ty][tx] = s; pm[ty][tx] = m;
    __syncthreads();
    if (ty == 0) {
        float st = ps[0][tx] + ps[1][tx] + ps[2][tx] + ps[3][tx];
        float mt = fmaxf(fmaxf(pm[0][tx], pm[1][tx]), fmaxf(pm[2][tx], pm[3][tx]));
        g_avgs[bb * HW + pix] = st * (1.f / (float)CC);
        g_maxs[bb * HW + pix] = mt;
    }
}

// ---------------- Kernel D/E fused: 7x7 conv + sigmoid + final scale ---------
// grid = 128 blocks, blockDim (128,4). ty==0 computes conv+sigmoid per pixel,
// then all threads stream x * ch_att * sig(sp) to out.
__global__ void sca_final(const float* __restrict__ x, const float* __restrict__ wsp,
                          float* __restrict__ out) {
    int bb   = blockIdx.x >> 5;
    int tile = blockIdx.x & 31;
    int tx = threadIdx.x, ty = threadIdx.y;
    int pix = tile * 128 + tx;
    __shared__ float ch[CC], wk[98], sig[128];
    int tid = ty * 128 + tx;
    if (tid < CC) ch[tid] = g_chatt[bb * CC + tid];
    else if (tid < CC + 98) wk[tid - CC] = wsp[tid - CC];
    __syncthreads();
    if (ty == 0) {
        int py = pix >> 6, px = pix & 63;
        float acc = 0.f;
        const float* as = g_avgs + bb * HW;
        const float* ms = g_maxs + bb * HW;
#pragma unroll
        for (int ky = 0; ky < 7; ++ky) {
            int iy = py + ky - 3;
            if (iy < 0 || iy >= HH) continue;
#pragma unroll
            for (int kx = 0; kx < 7; ++kx) {
                int ix = px + kx - 3;
                if (ix < 0 || ix >= WW) continue;
                int p2 = iy * WW + ix;
                acc += wk[ky * 7 + kx] * as[p2] + wk[49 + ky * 7 + kx] * ms[p2];
            }
        }
        sig[tx] = 1.f / (1.f + __expf(-acc));
    }
    __syncthreads();
    float sg = sig[tx];
    const float* xb = x + (size_t)bb * CC * HW + pix;
    float* ob       = out + (size_t)bb * CC * HW + pix;
    int c0 = ty * 64;
#pragma unroll 8
    for (int c = c0; c < c0 + 64; ++c)
        ob[c * HW] = xb[c * HW] * ch[c] * sg;
}

// ---------------- Guarded fallback: non-local attention (gamma != 0 only) ----
// setup_inputs() has gamma == 0 structurally, so these exit immediately;
// included so the kernel computes the full reference function for any gamma.
__global__ void sca_qkv(const float* __restrict__ gamma, const float* __restrict__ xcb,
                        const float* __restrict__ wq, const float* __restrict__ bq,
                        const float* __restrict__ wk_, const float* __restrict__ bk,
                        const float* __restrict__ wv, const float* __restrict__ bv) {
    if (*gamma == 0.f) return;
    int nth = gridDim.x * blockDim.x;
    int gt = blockIdx.x * blockDim.x + threadIdx.x;
    for (int idx = gt; idx < BB * C8 * HW; idx += nth) {
        int bb = idx / (C8 * HW);
        int r  = idx % (C8 * HW);
        int o = r / HW, pix = r % HW;
        float sq = bq[o], sk = bk[o];
        for (int c = 0; c < CC; ++c) {
            float xv = xcb[((size_t)bb * CC + c) * HW + pix];
            sq += wq[o * CC + c] * xv;
            sk += wk_[o * CC + c] * xv;
        }
        g_q[idx] = sq; g_k[idx] = sk;
    }
    for (int idx = gt; idx < BB * CC * HW; idx += nth) {
        int bb = idx / (CC * HW);
        int r  = idx % (CC * HW);
        int o = r / HW, pix = r % HW;
        float sv = bv[o];
        for (int c = 0; c < CC; ++c)
            sv += wv[o * CC + c] * xcb[((size_t)bb * CC + c) * HW + pix];
        g_v[idx] = sv;
    }
}

__global__ void sca_attn(const float* __restrict__ gamma, float* __restrict__ out) {
    float g = *gamma;
    if (g == 0.f) return;
    __shared__ float logits[HW];
    __shared__ float red[256];
    __shared__ float qi[C8];
    for (int row = blockIdx.x; row < BB * HW; row += gridDim.x) {
        int bb = row / HW, i = row % HW;
        if (threadIdx.x < C8) qi[threadIdx.x] = g_q[(bb * C8 + threadIdx.x) * HW + i];
        __syncthreads();
        float lm = -INFINITY;
        for (int j = threadIdx.x; j < HW; j += blockDim.x) {
            float s = 0.f;
            for (int d = 0; d < C8; ++d) s += qi[d] * g_k[(bb * C8 + d) * HW + j];
            logits[j] = s; lm = fmaxf(lm, s);
        }
        red[threadIdx.x] = lm; __syncthreads();
        for (int off = 128; off > 0; off >>= 1) {
            if (threadIdx.x < off) red[threadIdx.x] = fmaxf(red[threadIdx.x], red[threadIdx.x + off]);
            __syncthreads();
        }
        float mx = red[0];
        __syncthreads();
        float ls = 0.f;
        for (int j = threadIdx.x; j < HW; j += blockDim.x) {
            float e = expf(logits[j] - mx);
            logits[j] = e; ls += e;
        }
        red[threadIdx.x] = ls; __syncthreads();
        for (int off = 128; off > 0; off >>= 1) {
            if (threadIdx.x < off) red[threadIdx.x] += red[threadIdx.x + off];
            __syncthreads();
        }
        float inv = 1.f / red[0];
        __syncthreads();
        for (int c = threadIdx.x; c < CC; c += blockDim.x) {
            float s = 0.f;
            for (int j = 0; j < HW; ++j) s += g_v[((size_t)bb * CC + c) * HW + j] * logits[j];
            size_t oi = ((size_t)bb * CC + c) * HW + i;
            out[oi] = g * s * inv + out[oi];
        }
        __syncthreads();
    }
}

// ---------------- launch -----------------------------------------------------
extern "C" void kernel_launch(void* const* d_in, const int* in_sizes, int n_in,
                              void* d_out, int out_size) {
    const float* x     = (const float*)d_in[0];
    const float* w1    = (const float*)d_in[1];
    const float* w2    = (const float*)d_in[2];
    const float* w_sp  = (const float*)d_in[3];
    const float* wq    = (const float*)d_in[4];
    const float* bq    = (const float*)d_in[5];
    const float* wk    = (const float*)d_in[6];
    const float* bk    = (const float*)d_in[7];
    const float* wv    = (const float*)d_in[8];
    const float* bv    = (const float*)d_in[9];
    const float* gamma = (const float*)d_in[10];
    float* out = (float*)d_out;

    sca_pool_bc<<<BB * CC, 256>>>(x);
    sca_mlp<<<BB, 256>>>(w1, w2);
    sca_spstats<<<128, dim3(128, 4)>>>(x);
    sca_final<<<128, dim3(128, 4)>>>(x, w_sp, out);
    // guarded fallback (no-ops when gamma == 0, which setup_inputs guarantees)
    sca_qkv<<<148, 256>>>(gamma, out, wq, bq, wk, bk, wv, bv);
    sca_attn<<<148, 256>>>(gamma, out);
}